// round 3
// baseline (speedup 1.0000x reference)
#include <cuda_runtime.h>
#include <math.h>
#include <stdint.h>

// Problem constants
#define BATCH 8
#define CH    256
#define NQ    2048
#define MPTS  4096
#define KNN   10

static __device__ float g_Yqk[(size_t)BATCH * CH * NQ];
static __device__ float g_Yv [(size_t)BATCH * CH * NQ];
static __device__ float g_attn[(size_t)BATCH * NQ * NQ];
static __device__ float g_colsum[BATCH * NQ];
static __device__ float g_dbuf[(size_t)BATCH * CH * NQ];
static __device__ float g_feat[(size_t)BATCH * CH * NQ];
static __device__ float g_query[(size_t)BATCH * 3 * NQ];

// ---------------------------------------------------------------------------
// Tiled fp32 GEMM: 128x128 block tile, BK=16, 256 threads, 8x8 per thread.
// TRANSA=false: A is row-major MxK (A[m*lda+k]).
// TRANSA=true : A is stored KxM   (A[k*lda+m]) i.e. we compute A^T * B.
// MODE 0: C = acc
// MODE 1: C = acc + vec1[row]                        (bias)
// MODE 2: C = xres - acc / (1e-9 + vec1[col])        (x - x_r with colsum norm)
// MODE 3: C = xres + relu((acc+vec1[row])*s*gamma[row] + beta[row])  (BN+res)
// All dims are multiples of the tiles -> no bounds checks.
// ---------------------------------------------------------------------------
#define GBM 128
#define GBN 128
#define GBK 16

template<bool TRANSA, int MODE>
__global__ __launch_bounds__(256)
void gemm_kernel(const float* __restrict__ A, size_t sA,
                 const float* __restrict__ B, size_t sB,
                 float* __restrict__ Cout, size_t sC,
                 int M, int N, int K, int lda, int ldb, int ldc,
                 const float* __restrict__ xres, size_t sX,
                 const float* __restrict__ vec1, size_t sV,
                 const float* __restrict__ gamma,
                 const float* __restrict__ beta)
{
    const int b = blockIdx.z;
    A += (size_t)b * sA;
    B += (size_t)b * sB;
    Cout += (size_t)b * sC;
    const float* Xr = xres ? xres + (size_t)b * sX : nullptr;
    const float* V1 = vec1 ? vec1 + (size_t)b * sV : nullptr;

    __shared__ float As[GBK][GBM + 4];
    __shared__ float Bs[GBK][GBN + 4];

    const int tid = threadIdx.x;
    const int tm = tid >> 4;   // 0..15
    const int tn = tid & 15;   // 0..15
    const int row0 = blockIdx.y * GBM;
    const int col0 = blockIdx.x * GBN;

    float acc[8][8];
#pragma unroll
    for (int i = 0; i < 8; i++)
#pragma unroll
        for (int j = 0; j < 8; j++) acc[i][j] = 0.f;

    for (int k0 = 0; k0 < K; k0 += GBK) {
        // ---- load A tile ----
        if (TRANSA) {
#pragma unroll
            for (int i = 0; i < 2; i++) {
                int ff = tid + i * 256;          // 512 float4 total
                int kr = ff >> 5;                // 0..15
                int mc = (ff & 31) * 4;          // 0..124
                float4 v = *(const float4*)&A[(size_t)(k0 + kr) * lda + row0 + mc];
                *(float4*)&As[kr][mc] = v;
            }
        } else {
#pragma unroll
            for (int i = 0; i < 2; i++) {
                int ff = tid + i * 256;
                int r  = ff >> 2;                // 0..127
                int kc = (ff & 3) * 4;           // 0,4,8,12
                float4 v = *(const float4*)&A[(size_t)(row0 + r) * lda + k0 + kc];
                As[kc + 0][r] = v.x;
                As[kc + 1][r] = v.y;
                As[kc + 2][r] = v.z;
                As[kc + 3][r] = v.w;
            }
        }
        // ---- load B tile ----
#pragma unroll
        for (int i = 0; i < 2; i++) {
            int ff = tid + i * 256;
            int kr = ff >> 5;
            int nc = (ff & 31) * 4;
            float4 v = *(const float4*)&B[(size_t)(k0 + kr) * ldb + col0 + nc];
            *(float4*)&Bs[kr][nc] = v;
        }
        __syncthreads();

#pragma unroll
        for (int kk = 0; kk < GBK; kk++) {
            float a[8], bb[8];
            *(float4*)&a[0]  = *(float4*)&As[kk][tm * 8];
            *(float4*)&a[4]  = *(float4*)&As[kk][tm * 8 + 4];
            *(float4*)&bb[0] = *(float4*)&Bs[kk][tn * 8];
            *(float4*)&bb[4] = *(float4*)&Bs[kk][tn * 8 + 4];
#pragma unroll
            for (int i = 0; i < 8; i++)
#pragma unroll
                for (int j = 0; j < 8; j++)
                    acc[i][j] = fmaf(a[i], bb[j], acc[i][j]);
        }
        __syncthreads();
    }

    const float bnscale = 0.9999950000374996f;  // 1/sqrt(1+1e-5)
#pragma unroll
    for (int i = 0; i < 8; i++) {
        int r = row0 + tm * 8 + i;
        float rowbias = 0.f, g = 0.f, be = 0.f;
        if (MODE == 1 || MODE == 3) rowbias = V1[r];
        if (MODE == 3) { g = gamma[r]; be = beta[r]; }
#pragma unroll
        for (int j = 0; j < 8; j++) {
            int c = col0 + tn * 8 + j;
            float v = acc[i][j];
            if (MODE == 1) v += rowbias;
            if (MODE == 2) v = Xr[(size_t)r * ldc + c] - v / (1e-9f + V1[c]);
            if (MODE == 3) {
                v = (v + rowbias) * bnscale * g + be;
                v = Xr[(size_t)r * ldc + c] + fmaxf(v, 0.f);
            }
            Cout[(size_t)r * ldc + c] = v;
        }
    }
}

// ---------------------------------------------------------------------------
// Row softmax over attn rows (in place). One block per row, 256 threads x 8.
// ---------------------------------------------------------------------------
__global__ __launch_bounds__(256)
void softmax_rows(float* __restrict__ attn)
{
    float* row = attn + (size_t)blockIdx.x * NQ;
    const int t = threadIdx.x;
    float v[8];
    float mx = -1e30f;
#pragma unroll
    for (int i = 0; i < 8; i++) {
        v[i] = row[t + i * 256];
        mx = fmaxf(mx, v[i]);
    }
    __shared__ float red[8];
    __shared__ float red2[8];
#pragma unroll
    for (int off = 16; off; off >>= 1)
        mx = fmaxf(mx, __shfl_xor_sync(0xffffffffu, mx, off));
    if ((t & 31) == 0) red[t >> 5] = mx;
    __syncthreads();
    mx = red[0];
#pragma unroll
    for (int i = 1; i < 8; i++) mx = fmaxf(mx, red[i]);

    float s = 0.f;
#pragma unroll
    for (int i = 0; i < 8; i++) {
        v[i] = __expf(v[i] - mx);
        s += v[i];
    }
#pragma unroll
    for (int off = 16; off; off >>= 1)
        s += __shfl_xor_sync(0xffffffffu, s, off);
    if ((t & 31) == 0) red2[t >> 5] = s;
    __syncthreads();
    s = red2[0];
#pragma unroll
    for (int i = 1; i < 8; i++) s += red2[i];
    float inv = 1.f / s;
#pragma unroll
    for (int i = 0; i < 8; i++) row[t + i * 256] = v[i] * inv;
}

__global__ void zero_kernel(float* __restrict__ p, int n)
{
    int i = blockIdx.x * blockDim.x + threadIdx.x;
    if (i < n) p[i] = 0.f;
}

// colsum[b][m] = sum_n attn[b][n][m]; grid (B, NQ/256, NQ/256)
__global__ __launch_bounds__(256)
void colsum_kernel(const float* __restrict__ attn, float* __restrict__ cs)
{
    const int b = blockIdx.x;
    const int m = blockIdx.y * 256 + threadIdx.x;
    const int n0 = blockIdx.z * 256;
    const float* p = attn + ((size_t)b * NQ + n0) * NQ + m;
    float s = 0.f;
#pragma unroll 8
    for (int n = 0; n < 256; n++) s += p[(size_t)n * NQ];
    atomicAdd(&cs[b * NQ + m], s);
}

// query[b][j][n] = sum_c W_proj[j][c] * feat[b][c][n] + b_proj[j]
__global__ __launch_bounds__(256)
void query_kernel(const float* __restrict__ feat, const float* __restrict__ Wp,
                  const float* __restrict__ bp, float* __restrict__ q)
{
    const int n = blockIdx.x * 256 + threadIdx.x;
    const int b = blockIdx.y;
    const float* f = feat + (size_t)b * CH * NQ + n;
    float a0 = 0.f, a1 = 0.f, a2 = 0.f;
#pragma unroll 4
    for (int c = 0; c < CH; c++) {
        float fv = f[(size_t)c * NQ];
        a0 = fmaf(Wp[c], fv, a0);
        a1 = fmaf(Wp[CH + c], fv, a1);
        a2 = fmaf(Wp[2 * CH + c], fv, a2);
    }
    size_t o = (size_t)b * 3 * NQ + n;
    q[o]          = a0 + bp[0];
    q[o + NQ]     = a1 + bp[1];
    q[o + 2 * NQ] = a2 + bp[2];
}

// ---------------------------------------------------------------------------
// Soft projection: per query, top-10 nearest among 4096 DB points (held in
// shared), softmax(-d2/sigma) weighted average. One warp per query, 8 queries
// per warp per block. grid (BATCH, NQ/64), 256 threads.
// ---------------------------------------------------------------------------
__global__ __launch_bounds__(256)
void softproj_kernel(const float* __restrict__ pc,     // (B,3,M)
                     const float* __restrict__ query,  // (B,3,N)
                     const float* __restrict__ temp,   // scalar
                     float* __restrict__ out)          // (B,3,N)
{
    __shared__ float spx[MPTS];
    __shared__ float spy[MPTS];
    __shared__ float spz[MPTS];

    const int b = blockIdx.x;
    const float* p = pc + (size_t)b * 3 * MPTS;
    for (int i = threadIdx.x; i < MPTS; i += 256) {
        spx[i] = p[i];
        spy[i] = p[MPTS + i];
        spz[i] = p[2 * MPTS + i];
    }
    __syncthreads();

    const float t = temp[0];
    const float sigma = fmaxf(t * t, 1e-4f) + 1e-8f;
    const float invsig = 1.f / sigma;

    const int warp = threadIdx.x >> 5;
    const int lane = threadIdx.x & 31;
    const int qbase = blockIdx.y * 64;

    for (int qq = 0; qq < 8; ++qq) {
        const int n = qbase + warp * 8 + qq;
        const float qx = query[((size_t)b * 3 + 0) * NQ + n];
        const float qy = query[((size_t)b * 3 + 1) * NQ + n];
        const float qz = query[((size_t)b * 3 + 2) * NQ + n];

        float d[KNN];
        int   idx[KNN];
#pragma unroll
        for (int i = 0; i < KNN; i++) { d[i] = 1e30f; idx[i] = 0; }

        for (int m = lane; m < MPTS; m += 32) {
            float dx = spx[m] - qx;
            float dy = spy[m] - qy;
            float dz = spz[m] - qz;
            float dd = fmaf(dx, dx, fmaf(dy, dy, dz * dz));
            if (dd < d[KNN - 1]) {
                d[KNN - 1] = dd; idx[KNN - 1] = m;
#pragma unroll
                for (int j = KNN - 1; j > 0; --j) {
                    if (d[j] < d[j - 1]) {
                        float td = d[j]; d[j] = d[j - 1]; d[j - 1] = td;
                        int ti = idx[j]; idx[j] = idx[j - 1]; idx[j - 1] = ti;
                    }
                }
            }
        }

        // merge: extract global KNN smallest in increasing order
        float wsum = 0.f, ox = 0.f, oy = 0.f, oz = 0.f;
        float dmin = 0.f;
#pragma unroll
        for (int k = 0; k < KNN; k++) {
            float cd = d[0];
            int   ci = idx[0];
#pragma unroll
            for (int off = 16; off; off >>= 1) {
                float od = __shfl_xor_sync(0xffffffffu, cd, off);
                int   oi = __shfl_xor_sync(0xffffffffu, ci, off);
                if (od < cd || (od == cd && oi < ci)) { cd = od; ci = oi; }
            }
            if (k == 0) dmin = cd;
            float w = __expf(-(cd - dmin) * invsig);
            wsum += w;
            ox = fmaf(w, spx[ci], ox);
            oy = fmaf(w, spy[ci], oy);
            oz = fmaf(w, spz[ci], oz);
            bool iwin = (d[0] == cd && idx[0] == ci);
            unsigned bal = __ballot_sync(0xffffffffu, iwin);
            if (lane == (__ffs(bal) - 1)) {
#pragma unroll
                for (int j = 0; j < KNN - 1; j++) { d[j] = d[j + 1]; idx[j] = idx[j + 1]; }
                d[KNN - 1] = 1e30f; idx[KNN - 1] = 0;
            }
        }

        if (lane == 0) {
            float inv = 1.f / wsum;
            out[((size_t)b * 3 + 0) * NQ + n] = ox * inv;
            out[((size_t)b * 3 + 1) * NQ + n] = oy * inv;
            out[((size_t)b * 3 + 2) * NQ + n] = oz * inv;
        }
    }
}

// ---------------------------------------------------------------------------
extern "C" void kernel_launch(void* const* d_in, const int* in_sizes, int n_in,
                              void* d_out, int out_size)
{
    const float* x     = (const float*)d_in[0];
    const float* pc    = (const float*)d_in[1];
    const float* Wqk   = (const float*)d_in[2];
    const float* Wv    = (const float*)d_in[3];
    const float* bv    = (const float*)d_in[4];
    const float* Wt    = (const float*)d_in[5];
    const float* bt    = (const float*)d_in[6];
    const float* gamma = (const float*)d_in[7];
    const float* beta  = (const float*)d_in[8];
    const float* Wp    = (const float*)d_in[9];
    const float* bp    = (const float*)d_in[10];
    const float* temp  = (const float*)d_in[11];
    float* out = (float*)d_out;

    float *Yqk, *Yv, *attn, *colsum, *dbuf, *feat, *query;
    cudaGetSymbolAddress((void**)&Yqk,    g_Yqk);
    cudaGetSymbolAddress((void**)&Yv,     g_Yv);
    cudaGetSymbolAddress((void**)&attn,   g_attn);
    cudaGetSymbolAddress((void**)&colsum, g_colsum);
    cudaGetSymbolAddress((void**)&dbuf,   g_dbuf);
    cudaGetSymbolAddress((void**)&feat,   g_feat);
    cudaGetSymbolAddress((void**)&query,  g_query);

    const size_t CHNQ = (size_t)CH * NQ;
    const size_t NQNQ = (size_t)NQ * NQ;
    dim3 blk(256);
    dim3 gProj(NQ / GBN, CH / GBM, BATCH);   // (16,2,8)
    dim3 gE(NQ / GBN, NQ / GBM, BATCH);      // (16,16,8)

    // Yqk = Wqk @ x   (per batch)
    gemm_kernel<false, 0><<<gProj, blk>>>(Wqk, 0, x, CHNQ, Yqk, CHNQ,
                                          CH, NQ, CH, CH, NQ, NQ,
                                          nullptr, 0, nullptr, 0, nullptr, nullptr);
    // Yv = Wv @ x + bv
    gemm_kernel<false, 1><<<gProj, blk>>>(Wv, 0, x, CHNQ, Yv, CHNQ,
                                          CH, NQ, CH, CH, NQ, NQ,
                                          nullptr, 0, bv, 0, nullptr, nullptr);
    // energy = Yqk^T @ Yqk
    gemm_kernel<true, 0><<<gE, blk>>>(Yqk, CHNQ, Yqk, CHNQ, attn, NQNQ,
                                      NQ, NQ, CH, NQ, NQ, NQ,
                                      nullptr, 0, nullptr, 0, nullptr, nullptr);
    // row softmax in place
    softmax_rows<<<BATCH * NQ, 256>>>(attn);
    // colsum
    zero_kernel<<<(BATCH * NQ + 255) / 256, 256>>>(colsum, BATCH * NQ);
    colsum_kernel<<<dim3(BATCH, NQ / 256, NQ / 256), 256>>>(attn, colsum);
    // dbuf = x - (Yv @ attn) / (1e-9 + colsum)
    gemm_kernel<false, 2><<<gProj, blk>>>(Yv, CHNQ, attn, NQNQ, dbuf, CHNQ,
                                          CH, NQ, NQ, NQ, NQ, NQ,
                                          x, CHNQ, colsum, NQ, nullptr, nullptr);
    // feat = x + relu(BN(Wt @ dbuf + bt))
    gemm_kernel<false, 3><<<gProj, blk>>>(Wt, 0, dbuf, CHNQ, feat, CHNQ,
                                          CH, NQ, CH, CH, NQ, NQ,
                                          x, CHNQ, bt, 0, gamma, beta);
    // query = Wp @ feat + bp
    query_kernel<<<dim3(NQ / 256, BATCH), 256>>>(feat, Wp, bp, query);
    // soft projection
    softproj_kernel<<<dim3(BATCH, NQ / 64), 256>>>(pc, query, temp, out);
}

// round 5
// speedup vs baseline: 1.3754x; 1.3754x over previous
#include <cuda_runtime.h>
#include <math.h>
#include <stdint.h>

#define BATCH 8
#define CH    256
#define NQ    2048
#define MPTS  4096
#define KNN   10

static __device__ float g_Yqkt [(size_t)BATCH * NQ * CH];   // (b,n,c)
static __device__ float g_Yv   [(size_t)BATCH * CH * NQ];   // (b,c,n)
static __device__ float g_energy[(size_t)BATCH * NQ * NQ];  // (b,n,m)
static __device__ float g_attnT [(size_t)BATCH * NQ * NQ];  // (b,m,n)
static __device__ float g_rmax [BATCH * NQ];
static __device__ float g_rinv [BATCH * NQ];
static __device__ float g_colsum[BATCH * NQ];
static __device__ float g_dbufT[(size_t)BATCH * NQ * CH];   // (b,n,c)
static __device__ float g_feat [(size_t)BATCH * CH * NQ];   // (b,c,n)
static __device__ float g_query[(size_t)BATCH * 3 * NQ];

__device__ __forceinline__ uint32_t smem_u32(const void* p) {
    uint32_t a;
    asm("{ .reg .u64 t; cvta.to.shared.u64 t, %1; cvt.u32.u64 %0, t; }" : "=r"(a) : "l"(p));
    return a;
}
__device__ __forceinline__ uint32_t f2tf32(float f) {
    uint32_t r;
    asm("cvt.rna.tf32.f32 %0, %1;" : "=r"(r) : "f"(f));
    return r;
}
#define LDSM_X4(r0, r1, r2, r3, addr) \
    asm volatile("ldmatrix.sync.aligned.m8n8.x4.shared.b16 {%0,%1,%2,%3}, [%4];" \
        : "=r"(r0), "=r"(r1), "=r"(r2), "=r"(r3) : "r"(addr))
#define MMA4(d, a, bb) \
    asm volatile("mma.sync.aligned.m16n8k8.row.col.f32.tf32.tf32.f32 " \
        "{%0,%1,%2,%3}, {%4,%5,%6,%7}, {%8,%9}, {%0,%1,%2,%3};" \
        : "+f"((d)[0]), "+f"((d)[1]), "+f"((d)[2]), "+f"((d)[3]) \
        : "r"((a)[0]), "r"((a)[1]), "r"((a)[2]), "r"((a)[3]), \
          "r"((bb)[0]), "r"((bb)[1]))

// ===========================================================================
// mma.sync tf32 GEMM: D[128 x 128] = A(128,K) @ B(128,K)^T, both K-major.
// PASSES==3: 3xTF32 (hi/lo);  PASSES==1: plain tf32.
// MODE 0: energy[(b*NQ + a0+row)*NQ + boff+col] = acc
// MODE 2: dbufT[(b*NQ+m)*CH + c] = x[b][c][m] - acc/(1e-9+colsum[b][m])
// SMEM per stage: Ah(16K) Bh(16K) [Al(16K) Bl(16K)], SW128 swizzle, 2 stages.
// ===========================================================================
template<int PASSES, int MODE>
__global__ __launch_bounds__(256)
void mma_gemm(const float* __restrict__ Aall, size_t sA, int lda,
              const float* __restrict__ Ball, size_t sB, int ldb,
              float* __restrict__ Out, int KTOT,
              const float* __restrict__ xres, const float* __restrict__ colsum)
{
    extern __shared__ char DSM[];
    const int STAGE = (PASSES == 3) ? 65536 : 32768;
    const int b = blockIdx.z;
    const int a0 = blockIdx.x * 128;
    const int boff = blockIdx.y * 128;
    const float* Arow = Aall + (size_t)b * sA + (size_t)a0 * lda;
    const float* Brow = Ball + (size_t)b * sB + (size_t)boff * ldb;
    const int tid = threadIdx.x, lane = tid & 31;
    const int wm = (tid >> 5) >> 2, wn = (tid >> 5) & 3;
    const uint32_t sbase = smem_u32(DSM);

    float acc[4][4][4];
#pragma unroll
    for (int i = 0; i < 4; i++)
#pragma unroll
        for (int j = 0; j < 4; j++)
#pragma unroll
            for (int k = 0; k < 4; k++) acc[i][j][k] = 0.f;

    float4 pa[4], pb[4];
#pragma unroll
    for (int i = 0; i < 4; i++) {
        int idx = tid + i * 256, m = idx >> 3, j = idx & 7;
        pa[i] = *(const float4*)(Arow + (size_t)m * lda + j * 4);
        pb[i] = *(const float4*)(Brow + (size_t)m * ldb + j * 4);
    }

    const int NIT = KTOT / 32;
    for (int it = 0; it < NIT; it++) {
        const int s = it & 1;
        char* st = DSM + s * STAGE;
        // convert + store stage s
#pragma unroll
        for (int i = 0; i < 4; i++) {
            int idx = tid + i * 256, m = idx >> 3, j = idx & 7;
            uint32_t off = (uint32_t)(m * 128 + ((j * 16) ^ ((m & 7) * 16)));
            float4 v = pa[i];
            uint4 h;
            h.x = f2tf32(v.x); h.y = f2tf32(v.y); h.z = f2tf32(v.z); h.w = f2tf32(v.w);
            *(uint4*)(st + off) = h;
            if (PASSES == 3) {
                float4 l = make_float4(v.x - __uint_as_float(h.x), v.y - __uint_as_float(h.y),
                                       v.z - __uint_as_float(h.z), v.w - __uint_as_float(h.w));
                *(float4*)(st + 32768 + off) = l;
            }
            v = pb[i];
            h.x = f2tf32(v.x); h.y = f2tf32(v.y); h.z = f2tf32(v.z); h.w = f2tf32(v.w);
            *(uint4*)(st + 16384 + off) = h;
            if (PASSES == 3) {
                float4 l = make_float4(v.x - __uint_as_float(h.x), v.y - __uint_as_float(h.y),
                                       v.z - __uint_as_float(h.z), v.w - __uint_as_float(h.w));
                *(float4*)(st + 49152 + off) = l;
            }
        }
        __syncthreads();
        if (it + 1 < NIT) {
            int k0 = (it + 1) * 32;
#pragma unroll
            for (int i = 0; i < 4; i++) {
                int idx = tid + i * 256, m = idx >> 3, j = idx & 7;
                pa[i] = *(const float4*)(Arow + (size_t)m * lda + k0 + j * 4);
                pb[i] = *(const float4*)(Brow + (size_t)m * ldb + k0 + j * 4);
            }
        }
        const uint32_t Ah = sbase + s * STAGE, Bh = Ah + 16384;
        const uint32_t Al = Ah + 32768, Bl = Ah + 49152;
#pragma unroll
        for (int ks = 0; ks < 4; ks++) {
            uint32_t ahf[4][4], bhf[4][2], alf[4][4], blf[4][2];
            const uint32_t ca = (uint32_t)(ks * 32 + (lane & 16));
            const int ra = wm * 64 + (lane & 15);
#pragma unroll
            for (int mt = 0; mt < 4; mt++) {
                int r = ra + mt * 16;
                uint32_t o = (uint32_t)(r * 128) + (ca ^ (uint32_t)((r & 7) * 16));
                LDSM_X4(ahf[mt][0], ahf[mt][1], ahf[mt][2], ahf[mt][3], Ah + o);
                if (PASSES == 3)
                    LDSM_X4(alf[mt][0], alf[mt][1], alf[mt][2], alf[mt][3], Al + o);
            }
            const uint32_t cb = (uint32_t)(ks * 32 + ((lane & 8) << 1));
            const int rbb = wn * 32 + (lane & 7) + ((lane & 16) >> 1);
#pragma unroll
            for (int np = 0; np < 2; np++) {
                int r = rbb + np * 16;
                uint32_t o = (uint32_t)(r * 128) + (cb ^ (uint32_t)((r & 7) * 16));
                LDSM_X4(bhf[2 * np][0], bhf[2 * np][1], bhf[2 * np + 1][0], bhf[2 * np + 1][1], Bh + o);
                if (PASSES == 3)
                    LDSM_X4(blf[2 * np][0], blf[2 * np][1], blf[2 * np + 1][0], blf[2 * np + 1][1], Bl + o);
            }
#pragma unroll
            for (int mt = 0; mt < 4; mt++)
#pragma unroll
                for (int nt = 0; nt < 4; nt++) {
                    MMA4(acc[mt][nt], ahf[mt], bhf[nt]);
                    if (PASSES == 3) {
                        MMA4(acc[mt][nt], ahf[mt], blf[nt]);
                        MMA4(acc[mt][nt], alf[mt], bhf[nt]);
                    }
                }
        }
        __syncthreads();
    }

    const int gid = lane >> 2, tig = lane & 3;
    if (MODE == 0) {
#pragma unroll
        for (int mt = 0; mt < 4; mt++) {
            int row = a0 + wm * 64 + mt * 16 + gid;
#pragma unroll
            for (int nt = 0; nt < 4; nt++) {
                int col = boff + wn * 32 + nt * 8 + 2 * tig;
                float* p = Out + ((size_t)b * NQ + row) * NQ + col;
                *(float2*)p = make_float2(acc[mt][nt][0], acc[mt][nt][1]);
                *(float2*)(p + (size_t)8 * NQ) = make_float2(acc[mt][nt][2], acc[mt][nt][3]);
            }
        }
    } else {
        const float* xb = xres + (size_t)b * CH * NQ;
#pragma unroll
        for (int mt = 0; mt < 4; mt++) {
            int m0r = a0 + wm * 64 + mt * 16 + gid;
            float inv0 = 1.f / (1e-9f + colsum[b * NQ + m0r]);
            float inv1 = 1.f / (1e-9f + colsum[b * NQ + m0r + 8]);
            float* o0 = Out + ((size_t)b * NQ + m0r) * CH;
            float* o1 = o0 + (size_t)8 * CH;
#pragma unroll
            for (int nt = 0; nt < 4; nt++) {
                int c = boff + wn * 32 + nt * 8 + 2 * tig;
                o0[c]     = xb[(size_t)c * NQ + m0r]       - acc[mt][nt][0] * inv0;
                o0[c + 1] = xb[(size_t)(c + 1) * NQ + m0r] - acc[mt][nt][1] * inv0;
                o1[c]     = xb[(size_t)c * NQ + m0r + 8]       - acc[mt][nt][2] * inv1;
                o1[c + 1] = xb[(size_t)(c + 1) * NQ + m0r + 8] - acc[mt][nt][3] * inv1;
            }
        }
    }
}

// ===========================================================================
// SIMT fp32 GEMM 128x128x16 for the C=256-K projections.
// MODE 1: C=acc+bias[row]; MODE 3: C=x+relu(BN(acc+bias)); MODE 4: C^T write
// ===========================================================================
#define GBK 16
template<bool TRANSB, int MODE>
__global__ __launch_bounds__(256)
void gemm_kernel(const float* __restrict__ A, size_t sA,
                 const float* __restrict__ B, size_t sB,
                 float* __restrict__ Cout, size_t sC,
                 int K, int lda, int ldb, int ldc,
                 const float* __restrict__ xres, size_t sX,
                 const float* __restrict__ vec1,
                 const float* __restrict__ gamma, const float* __restrict__ beta)
{
    const int b = blockIdx.z;
    A += (size_t)b * sA; B += (size_t)b * sB; Cout += (size_t)b * sC;
    const float* Xr = xres ? xres + (size_t)b * sX : nullptr;

    __shared__ float As[GBK][132];
    __shared__ float Bs[GBK][132];
    const int tid = threadIdx.x;
    const int tm = tid >> 4, tn = tid & 15;
    const int row0 = blockIdx.y * 128, col0 = blockIdx.x * 128;

    float acc[8][8];
#pragma unroll
    for (int i = 0; i < 8; i++)
#pragma unroll
        for (int j = 0; j < 8; j++) acc[i][j] = 0.f;

    for (int k0 = 0; k0 < K; k0 += GBK) {
#pragma unroll
        for (int i = 0; i < 2; i++) {
            int ff = tid + i * 256;
            int r = ff >> 2, kc = (ff & 3) * 4;
            float4 v = *(const float4*)&A[(size_t)(row0 + r) * lda + k0 + kc];
            As[kc][r] = v.x; As[kc + 1][r] = v.y; As[kc + 2][r] = v.z; As[kc + 3][r] = v.w;
        }
        if (TRANSB) {
#pragma unroll
            for (int i = 0; i < 2; i++) {
                int ff = tid + i * 256;
                int r = ff >> 2, kc = (ff & 3) * 4;
                float4 v = *(const float4*)&B[(size_t)(col0 + r) * ldb + k0 + kc];
                Bs[kc][r] = v.x; Bs[kc + 1][r] = v.y; Bs[kc + 2][r] = v.z; Bs[kc + 3][r] = v.w;
            }
        } else {
#pragma unroll
            for (int i = 0; i < 2; i++) {
                int ff = tid + i * 256;
                int kr = ff >> 5, nc = (ff & 31) * 4;
                *(float4*)&Bs[kr][nc] = *(const float4*)&B[(size_t)(k0 + kr) * ldb + col0 + nc];
            }
        }
        __syncthreads();
#pragma unroll
        for (int kk = 0; kk < GBK; kk++) {
            float a[8], bb[8];
            *(float4*)&a[0] = *(float4*)&As[kk][tm * 8];
            *(float4*)&a[4] = *(float4*)&As[kk][tm * 8 + 4];
            *(float4*)&bb[0] = *(float4*)&Bs[kk][tn * 8];
            *(float4*)&bb[4] = *(float4*)&Bs[kk][tn * 8 + 4];
#pragma unroll
            for (int i = 0; i < 8; i++)
#pragma unroll
                for (int j = 0; j < 8; j++) acc[i][j] = fmaf(a[i], bb[j], acc[i][j]);
        }
        __syncthreads();
    }

    if (MODE == 4) {
#pragma unroll
        for (int j = 0; j < 8; j++) {
            int c = col0 + tn * 8 + j;
            *(float4*)&Cout[(size_t)c * ldc + row0 + tm * 8] =
                make_float4(acc[0][j], acc[1][j], acc[2][j], acc[3][j]);
            *(float4*)&Cout[(size_t)c * ldc + row0 + tm * 8 + 4] =
                make_float4(acc[4][j], acc[5][j], acc[6][j], acc[7][j]);
        }
        return;
    }
    const float bns = 0.9999950000374996f;
#pragma unroll
    for (int i = 0; i < 8; i++) {
        int r = row0 + tm * 8 + i;
        float rb = vec1[r], g = 0.f, be = 0.f;
        if (MODE == 3) { g = gamma[r]; be = beta[r]; }
#pragma unroll
        for (int j = 0; j < 8; j++) {
            int c = col0 + tn * 8 + j;
            float v = acc[i][j];
            if (MODE == 1) v += rb;
            if (MODE == 3) {
                v = (v + rb) * bns * g + be;
                v = Xr[(size_t)r * ldc + c] + fmaxf(v, 0.f);
            }
            Cout[(size_t)r * ldc + c] = v;
        }
    }
}

__global__ __launch_bounds__(256)
void rowstat(const float* __restrict__ e, float* __restrict__ rmax, float* __restrict__ rinv)
{
    const float* row = e + (size_t)blockIdx.x * NQ;
    const int t = threadIdx.x;
    float v[8], mx = -1e30f;
#pragma unroll
    for (int i = 0; i < 8; i++) { v[i] = row[t + i * 256]; mx = fmaxf(mx, v[i]); }
    __shared__ float red[8], red2[8];
#pragma unroll
    for (int off = 16; off; off >>= 1) mx = fmaxf(mx, __shfl_xor_sync(~0u, mx, off));
    if ((t & 31) == 0) red[t >> 5] = mx;
    __syncthreads();
    mx = red[0];
#pragma unroll
    for (int i = 1; i < 8; i++) mx = fmaxf(mx, red[i]);
    float s = 0.f;
#pragma unroll
    for (int i = 0; i < 8; i++) s += __expf(v[i] - mx);
#pragma unroll
    for (int off = 16; off; off >>= 1) s += __shfl_xor_sync(~0u, s, off);
    if ((t & 31) == 0) red2[t >> 5] = s;
    __syncthreads();
    if (t == 0) {
        s = red2[0];
#pragma unroll
        for (int i = 1; i < 8; i++) s += red2[i];
        rmax[blockIdx.x] = mx;
        rinv[blockIdx.x] = 1.f / s;
    }
}

__global__ void zero_kernel(float* __restrict__ p, int n)
{
    int i = blockIdx.x * blockDim.x + threadIdx.x;
    if (i < n) p[i] = 0.f;
}

__global__ __launch_bounds__(256)
void attn_transpose(const float* __restrict__ energy, const float* __restrict__ rmax,
                    const float* __restrict__ rinv, float* __restrict__ attnT,
                    float* __restrict__ colsum)
{
    extern __shared__ float s[];   // 128 x 129
    const int b = blockIdx.z, n0 = blockIdx.y * 128, m0 = blockIdx.x * 128;
    const int t = threadIdx.x;
    const int bn = b * NQ + n0;
    const float* E = energy + ((size_t)b * NQ + n0) * NQ + m0;
#pragma unroll 8
    for (int i = 0; i < 64; i++) {
        int idx = t + i * 256;
        int r = idx >> 7, c = idx & 127;
        s[r * 129 + c] = __expf(E[(size_t)r * NQ + c] - rmax[bn + r]) * rinv[bn + r];
    }
    __syncthreads();
    const int j = t >> 1, h = t & 1;
    float* orow = attnT + ((size_t)b * NQ + m0 + j) * NQ + n0 + h * 64;
    float sum = 0.f;
#pragma unroll
    for (int i = 0; i < 64; i += 4) {
        float4 v;
        v.x = s[(h * 64 + i) * 129 + j];     v.y = s[(h * 64 + i + 1) * 129 + j];
        v.z = s[(h * 64 + i + 2) * 129 + j]; v.w = s[(h * 64 + i + 3) * 129 + j];
        sum += v.x + v.y + v.z + v.w;
        *(float4*)&orow[i] = v;
    }
    atomicAdd(&colsum[b * NQ + m0 + j], sum);
}

__global__ __launch_bounds__(256)
void query_kernel(const float* __restrict__ feat, const float* __restrict__ Wp,
                  const float* __restrict__ bp, float* __restrict__ q)
{
    const int n = blockIdx.x * 256 + threadIdx.x;
    const int b = blockIdx.y;
    const float* f = feat + (size_t)b * CH * NQ + n;
    float a0 = 0.f, a1 = 0.f, a2 = 0.f;
#pragma unroll 4
    for (int c = 0; c < CH; c++) {
        float fv = f[(size_t)c * NQ];
        a0 = fmaf(Wp[c], fv, a0);
        a1 = fmaf(Wp[CH + c], fv, a1);
        a2 = fmaf(Wp[2 * CH + c], fv, a2);
    }
    size_t o = (size_t)b * 3 * NQ + n;
    q[o] = a0 + bp[0]; q[o + NQ] = a1 + bp[1]; q[o + 2 * NQ] = a2 + bp[2];
}

__global__ __launch_bounds__(256)
void softproj_kernel(const float* __restrict__ pc, const float* __restrict__ query,
                     const float* __restrict__ temp, float* __restrict__ out)
{
    __shared__ float spx[MPTS], spy[MPTS], spz[MPTS];
    const int b = blockIdx.x;
    const float* p = pc + (size_t)b * 3 * MPTS;
    for (int i = threadIdx.x; i < MPTS; i += 256) {
        spx[i] = p[i]; spy[i] = p[MPTS + i]; spz[i] = p[2 * MPTS + i];
    }
    __syncthreads();

    const float t = temp[0];
    const float invsig = 1.f / (fmaxf(t * t, 1e-4f) + 1e-8f);
    const int warp = threadIdx.x >> 5, lane = threadIdx.x & 31;
    const int qbase = blockIdx.y * 64;

    for (int qq = 0; qq < 8; ++qq) {
        const int n = qbase + warp * 8 + qq;
        const float qx = query[((size_t)b * 3) * NQ + n];
        const float qy = query[((size_t)b * 3 + 1) * NQ + n];
        const float qz = query[((size_t)b * 3 + 2) * NQ + n];

        float d[KNN]; int idx[KNN];
#pragma unroll
        for (int i = 0; i < KNN; i++) { d[i] = 1e30f; idx[i] = 0; }
        for (int m = lane; m < MPTS; m += 32) {
            float dx = spx[m] - qx, dy = spy[m] - qy, dz = spz[m] - qz;
            float dd = fmaf(dx, dx, fmaf(dy, dy, dz * dz));
            if (dd < d[KNN - 1]) {
                d[KNN - 1] = dd; idx[KNN - 1] = m;
#pragma unroll
                for (int j = KNN - 1; j > 0; --j)
                    if (d[j] < d[j - 1]) {
                        float td = d[j]; d[j] = d[j - 1]; d[j - 1] = td;
                        int ti = idx[j]; idx[j] = idx[j - 1]; idx[j - 1] = ti;
                    }
            }
        }
        float wsum = 0.f, ox = 0.f, oy = 0.f, oz = 0.f, dmin = 0.f;
#pragma unroll
        for (int k = 0; k < KNN; k++) {
            float cd = d[0]; int ci = idx[0];
#pragma unroll
            for (int off = 16; off; off >>= 1) {
                float od = __shfl_xor_sync(~0u, cd, off);
                int   oi = __shfl_xor_sync(~0u, ci, off);
                if (od < cd || (od == cd && oi < ci)) { cd = od; ci = oi; }
            }
            if (k == 0) dmin = cd;
            float w = __expf(-(cd - dmin) * invsig);
            wsum += w;
            ox = fmaf(w, spx[ci], ox); oy = fmaf(w, spy[ci], oy); oz = fmaf(w, spz[ci], oz);
            bool iwin = (d[0] == cd && idx[0] == ci);
            unsigned bal = __ballot_sync(~0u, iwin);
            if (lane == (__ffs(bal) - 1)) {
#pragma unroll
                for (int j = 0; j < KNN - 1; j++) { d[j] = d[j + 1]; idx[j] = idx[j + 1]; }
                d[KNN - 1] = 1e30f; idx[KNN - 1] = 0;
            }
        }
        if (lane == 0) {
            float inv = 1.f / wsum;
            out[((size_t)b * 3) * NQ + n] = ox * inv;
            out[((size_t)b * 3 + 1) * NQ + n] = oy * inv;
            out[((size_t)b * 3 + 2) * NQ + n] = oz * inv;
        }
    }
}

// ---------------------------------------------------------------------------
extern "C" void kernel_launch(void* const* d_in, const int* in_sizes, int n_in,
                              void* d_out, int out_size)
{
    const float* x     = (const float*)d_in[0];
    const float* pc    = (const float*)d_in[1];
    const float* Wqk   = (const float*)d_in[2];
    const float* Wv    = (const float*)d_in[3];
    const float* bv    = (const float*)d_in[4];
    const float* Wt    = (const float*)d_in[5];
    const float* bt    = (const float*)d_in[6];
    const float* gamma = (const float*)d_in[7];
    const float* beta  = (const float*)d_in[8];
    const float* Wp    = (const float*)d_in[9];
    const float* bp    = (const float*)d_in[10];
    const float* temp  = (const float*)d_in[11];
    float* out = (float*)d_out;

    float *Yqkt, *Yv, *energy, *attnT, *rmx, *rin, *colsum, *dbufT, *feat, *query;
    cudaGetSymbolAddress((void**)&Yqkt,   g_Yqkt);
    cudaGetSymbolAddress((void**)&Yv,     g_Yv);
    cudaGetSymbolAddress((void**)&energy, g_energy);
    cudaGetSymbolAddress((void**)&attnT,  g_attnT);
    cudaGetSymbolAddress((void**)&rmx,    g_rmax);
    cudaGetSymbolAddress((void**)&rin,    g_rinv);
    cudaGetSymbolAddress((void**)&colsum, g_colsum);
    cudaGetSymbolAddress((void**)&dbufT,  g_dbufT);
    cudaGetSymbolAddress((void**)&feat,   g_feat);
    cudaGetSymbolAddress((void**)&query,  g_query);

    const size_t CHNQ = (size_t)CH * NQ;
    const size_t NQNQ = (size_t)NQ * NQ;
    const size_t NQCH = (size_t)NQ * CH;

    cudaFuncSetAttribute(mma_gemm<3, 0>, cudaFuncAttributeMaxDynamicSharedMemorySize, 131072);
    cudaFuncSetAttribute(mma_gemm<1, 2>, cudaFuncAttributeMaxDynamicSharedMemorySize, 65536);
    cudaFuncSetAttribute(attn_transpose, cudaFuncAttributeMaxDynamicSharedMemorySize, 66048);

    dim3 blk(256);
    // Yqkt = (Wqk @ x)^T   -> (b,n,c)
    gemm_kernel<false, 4><<<dim3(16, 2, 8), blk>>>(Wqk, 0, x, CHNQ, Yqkt, NQCH,
        CH, CH, NQ, CH, nullptr, 0, nullptr, nullptr, nullptr);
    // Yv = Wv @ x + bv     -> (b,c,n)
    gemm_kernel<false, 1><<<dim3(16, 2, 8), blk>>>(Wv, 0, x, CHNQ, Yv, CHNQ,
        CH, CH, NQ, NQ, nullptr, 0, bv, nullptr, nullptr);
    // energy[b][n][m] = Yqkt[n]·Yqkt[m]   (mma.sync 3xTF32)
    mma_gemm<3, 0><<<dim3(16, 16, 8), blk, 131072>>>(
        Yqkt, NQCH, CH, Yqkt, NQCH, CH, energy, CH, nullptr, nullptr);
    // softmax stats + transpose/colsum
    rowstat<<<BATCH * NQ, 256>>>(energy, rmx, rin);
    zero_kernel<<<(BATCH * NQ + 255) / 256, 256>>>(colsum, BATCH * NQ);
    attn_transpose<<<dim3(16, 16, 8), blk, 66048>>>(energy, rmx, rin, attnT, colsum);
    // dbufT[b][m][c] = x[b][c][m] - (attnT[m]·Yv[c]) / (1e-9+colsum[m])
    mma_gemm<1, 2><<<dim3(16, 2, 8), blk, 65536>>>(
        attnT, NQNQ, NQ, Yv, CHNQ, NQ, dbufT, NQ, x, colsum);
    // feat = x + relu(BN(Wt @ dbufT^T + bt))
    gemm_kernel<true, 3><<<dim3(16, 2, 8), blk>>>(Wt, 0, dbufT, NQCH, feat, CHNQ,
        CH, CH, CH, NQ, x, CHNQ, bt, gamma, beta);
    // query + soft projection
    query_kernel<<<dim3(NQ / 256, BATCH), 256>>>(feat, Wp, bp, query);
    softproj_kernel<<<dim3(BATCH, NQ / 64), 256>>>(pc, query, temp, out);
}